// round 1
// baseline (speedup 1.0000x reference)
#include <cuda_runtime.h>
#include <math.h>

#define BB   2
#define SS   2048
#define DD   1024
#define NH   16
#define DK   64
#define MTOT (BB * SS)        // 4096
#define NQKV (3 * DD)         // 3072

// Scratch (static device globals — allowed; no cudaMalloc anywhere)
__device__ float g_x[(size_t)MTOT * DD];      // 16 MB: query + pos
__device__ float g_qkv[(size_t)MTOT * NQKV];  // 48 MB: qkv projection
__device__ float g_o[(size_t)MTOT * DD];      // 16 MB: attention output

// ---------------------------------------------------------------------------
// x = query + pos_emb  (broadcast over batch; S*D is a power of two)
// ---------------------------------------------------------------------------
__global__ void add_pos_kernel(const float* __restrict__ q,
                               const float* __restrict__ pos,
                               float* __restrict__ x) {
    int i4 = (blockIdx.x * blockDim.x + threadIdx.x) * 4;
    float4 a = *(const float4*)(q + i4);
    float4 p = *(const float4*)(pos + (i4 & (SS * DD - 1)));
    a.x += p.x; a.y += p.y; a.z += p.z; a.w += p.w;
    *(float4*)(x + i4) = a;
}

// ---------------------------------------------------------------------------
// fp32 SGEMM: C[M,N] = A[M,K] @ B[K,N], row-major, all dims multiples of 128/8.
// 128x128 block tile, BK=8, 256 threads, 8x8 micro-tile per thread.
// ---------------------------------------------------------------------------
__global__ __launch_bounds__(256, 2)
void sgemm_kernel(int M, int N, int K,
                  const float* __restrict__ A,
                  const float* __restrict__ B,
                  float* __restrict__ C) {
    __shared__ float As[8][128];   // transposed A tile: As[k][m]
    __shared__ float Bs[8][128];   // natural B tile:    Bs[k][n]

    int tid = threadIdx.x;
    int tx = tid & 15;             // 0..15 -> col group
    int ty = tid >> 4;             // 0..15 -> row group
    int row0 = blockIdx.y * 128;
    int col0 = blockIdx.x * 128;

    int aRow = tid >> 1;           // 0..127
    int aCol = (tid & 1) * 4;      // 0 or 4
    int bRow = tid >> 5;           // 0..7
    int bCol = (tid & 31) * 4;     // 0..124

    const float* Ap = A + (size_t)(row0 + aRow) * K + aCol;
    const float* Bp = B + (size_t)bRow * N + col0 + bCol;

    float acc[8][8] = {};

    for (int k0 = 0; k0 < K; k0 += 8) {
        float4 av = *(const float4*)Ap;
        float4 bv = *(const float4*)Bp;
        As[aCol + 0][aRow] = av.x;
        As[aCol + 1][aRow] = av.y;
        As[aCol + 2][aRow] = av.z;
        As[aCol + 3][aRow] = av.w;
        *(float4*)&Bs[bRow][bCol] = bv;
        __syncthreads();

#pragma unroll
        for (int kk = 0; kk < 8; kk++) {
            float a[8], b[8];
            *(float4*)&a[0] = *(const float4*)&As[kk][ty * 8];
            *(float4*)&a[4] = *(const float4*)&As[kk][ty * 8 + 4];
            *(float4*)&b[0] = *(const float4*)&Bs[kk][tx * 8];
            *(float4*)&b[4] = *(const float4*)&Bs[kk][tx * 8 + 4];
#pragma unroll
            for (int i = 0; i < 8; i++)
#pragma unroll
                for (int j = 0; j < 8; j++)
                    acc[i][j] += a[i] * b[j];
        }
        __syncthreads();
        Ap += 8;
        Bp += (size_t)8 * N;
    }

#pragma unroll
    for (int i = 0; i < 8; i++) {
        float* Cp = C + (size_t)(row0 + ty * 8 + i) * N + col0 + tx * 8;
        *(float4*)Cp       = make_float4(acc[i][0], acc[i][1], acc[i][2], acc[i][3]);
        *(float4*)(Cp + 4) = make_float4(acc[i][4], acc[i][5], acc[i][6], acc[i][7]);
    }
}

// ---------------------------------------------------------------------------
// Flash attention (fp32). One block per (b, h, 64-row q tile).
// 256 threads; each computes a 4x4 micro-tile of the 64x64 score / 64x64 O tile.
// qkv layout per row: [h][{q,k,v}][d]  (h*192 + which*64 + d)
// ---------------------------------------------------------------------------
#define ATTN_SMEM_FLOATS (4096 /*Qs*/ + 4096 /*Ks*/ + 4096 /*Vs*/ + 4160 /*Ss*/ + 4096 /*Pt*/ + 64 + 64)
#define ATTN_SMEM_BYTES  (ATTN_SMEM_FLOATS * 4)

__global__ __launch_bounds__(256, 2)
void attn_kernel(const float* __restrict__ qkv, float* __restrict__ o) {
    extern __shared__ float sm[];
    float* Qs    = sm;              // [d][m]   4096
    float* Ks    = sm + 4096;       // [d][n]   4096
    float* Vs    = sm + 8192;       // [n][d]   4096
    float* Ss    = sm + 12288;      // [m][n] pad 65 -> 4160
    float* Pt    = sm + 16448;      // [n][m]   4096
    float* alphs = sm + 20544;      // 64
    float* linv  = sm + 20608;      // 64

    int q0 = blockIdx.x * 64;
    int h  = blockIdx.y;
    int b  = blockIdx.z;
    int tid = threadIdx.x;
    int tx = tid & 15;   // col group (n or d dim), 4 wide
    int ty = tid >> 4;   // row group (m dim), 4 wide

    const float scale = 0.125f;  // 1/sqrt(64)

    // Load Q tile (scaled), transposed into Qs[d][m]
    const float* Qg = qkv + (size_t)(b * SS + q0) * NQKV + h * 3 * DK;
    for (int f = tid; f < 1024; f += 256) {
        int m = f >> 4;
        int d = (f & 15) * 4;
        float4 v = *(const float4*)(Qg + (size_t)m * NQKV + d);
        Qs[(d + 0) * 64 + m] = v.x * scale;
        Qs[(d + 1) * 64 + m] = v.y * scale;
        Qs[(d + 2) * 64 + m] = v.z * scale;
        Qs[(d + 3) * 64 + m] = v.w * scale;
    }

    float m_run = -INFINITY, l_run = 0.f;  // valid in threads tid<64 (one per row)
    float o_acc[4][4];
#pragma unroll
    for (int i = 0; i < 4; i++)
#pragma unroll
        for (int j = 0; j < 4; j++) o_acc[i][j] = 0.f;

    __syncthreads();

    for (int t0 = 0; t0 < SS; t0 += 64) {
        // Load K (transposed) and V (natural) tiles
        const float* Kg = qkv + (size_t)(b * SS + t0) * NQKV + h * 3 * DK + DK;
        const float* Vg = Kg + DK;
        for (int f = tid; f < 1024; f += 256) {
            int n = f >> 4;
            int d = (f & 15) * 4;
            float4 kv = *(const float4*)(Kg + (size_t)n * NQKV + d);
            Ks[(d + 0) * 64 + n] = kv.x;
            Ks[(d + 1) * 64 + n] = kv.y;
            Ks[(d + 2) * 64 + n] = kv.z;
            Ks[(d + 3) * 64 + n] = kv.w;
            float4 vv = *(const float4*)(Vg + (size_t)n * NQKV + d);
            *(float4*)(Vs + n * 64 + d) = vv;
        }
        __syncthreads();

        // Score GEMM: S[m][n] = sum_d Qs[d][m] * Ks[d][n]
        float s_acc[4][4];
#pragma unroll
        for (int i = 0; i < 4; i++)
#pragma unroll
            for (int j = 0; j < 4; j++) s_acc[i][j] = 0.f;

#pragma unroll 8
        for (int d = 0; d < 64; d++) {
            float a[4], bb[4];
            *(float4*)a  = *(const float4*)(Qs + d * 64 + ty * 4);
            *(float4*)bb = *(const float4*)(Ks + d * 64 + tx * 4);
#pragma unroll
            for (int i = 0; i < 4; i++)
#pragma unroll
                for (int j = 0; j < 4; j++)
                    s_acc[i][j] += a[i] * bb[j];
        }
#pragma unroll
        for (int i = 0; i < 4; i++)
#pragma unroll
            for (int j = 0; j < 4; j++)
                Ss[(ty * 4 + i) * 65 + tx * 4 + j] = s_acc[i][j];
        __syncthreads();

        // Online softmax: one thread per q row
        if (tid < 64) {
            int r = tid;
            float mt = m_run;
#pragma unroll 8
            for (int j = 0; j < 64; j++) mt = fmaxf(mt, Ss[r * 65 + j]);
            float al = __expf(m_run - mt);   // first tile: exp(-inf)=0
            float sum = 0.f;
#pragma unroll 8
            for (int j = 0; j < 64; j++) {
                float p = __expf(Ss[r * 65 + j] - mt);
                Pt[j * 64 + r] = p;
                sum += p;
            }
            l_run = l_run * al + sum;
            m_run = mt;
            alphs[r] = al;
        }
        __syncthreads();

        // O update: O = O*alpha + P @ V
        float al[4];
#pragma unroll
        for (int i = 0; i < 4; i++) al[i] = alphs[ty * 4 + i];
#pragma unroll
        for (int i = 0; i < 4; i++)
#pragma unroll
            for (int j = 0; j < 4; j++) o_acc[i][j] *= al[i];

#pragma unroll 8
        for (int k = 0; k < 64; k++) {
            float a[4], bb[4];
            *(float4*)a  = *(const float4*)(Pt + k * 64 + ty * 4);
            *(float4*)bb = *(const float4*)(Vs + k * 64 + tx * 4);
#pragma unroll
            for (int i = 0; i < 4; i++)
#pragma unroll
                for (int j = 0; j < 4; j++)
                    o_acc[i][j] += a[i] * bb[j];
        }
        __syncthreads();  // protect Ks/Vs/Ss/Pt before next tile load
    }

    if (tid < 64) linv[tid] = 1.0f / l_run;
    __syncthreads();

    // Write O: (b, s=q0+m, h*64+d)
#pragma unroll
    for (int i = 0; i < 4; i++) {
        float li = linv[ty * 4 + i];
        float4 v = make_float4(o_acc[i][0] * li, o_acc[i][1] * li,
                               o_acc[i][2] * li, o_acc[i][3] * li);
        *(float4*)(o + (size_t)(b * SS + q0 + ty * 4 + i) * DD + h * DK + tx * 4) = v;
    }
}

// ---------------------------------------------------------------------------
// Launch
// ---------------------------------------------------------------------------
extern "C" void kernel_launch(void* const* d_in, const int* in_sizes, int n_in,
                              void* d_out, int out_size) {
    const float* query = (const float*)d_in[0];
    const float* pos   = (const float*)d_in[1];
    const float* w_qkv = (const float*)d_in[2];
    const float* w_out = (const float*)d_in[3];
    float* out = (float*)d_out;

    float *xp, *qkvp, *op;
    cudaGetSymbolAddress((void**)&xp, g_x);
    cudaGetSymbolAddress((void**)&qkvp, g_qkv);
    cudaGetSymbolAddress((void**)&op, g_o);

    cudaFuncSetAttribute(attn_kernel,
                         cudaFuncAttributeMaxDynamicSharedMemorySize,
                         ATTN_SMEM_BYTES);

    // 1) x = query + pos
    add_pos_kernel<<<(MTOT * DD) / 4 / 256, 256>>>(query, pos, xp);

    // 2) qkv = x @ w_qkv  (4096 x 3072 x 1024)
    sgemm_kernel<<<dim3(NQKV / 128, MTOT / 128), 256>>>(MTOT, NQKV, DD, xp, w_qkv, qkvp);

    // 3) flash attention -> o (4096 x 1024)
    attn_kernel<<<dim3(SS / 64, NH, BB), 256, ATTN_SMEM_BYTES>>>(qkvp, op);

    // 4) out = o @ w_out  (4096 x 1024 x 1024)
    sgemm_kernel<<<dim3(DD / 128, MTOT / 128), 256>>>(MTOT, DD, DD, op, w_out, out);
}